// round 16
// baseline (speedup 1.0000x reference)
#include <cuda_runtime.h>

#define NB 32
#define S 64
#define S2 (S*S)
#define S3 (S*S*S)
#define NPTS 65536
#define GRID_ELEMS (NB*S3)
#define N_TICKETS 12288          // 8192 scatter + 2048 convxy + 2048 convz
#define WORKERS 740              // ~5 blocks/SM persistent

// 21-tap Gaussian, sigma=3, normalized (double-precision derived), + zero pad
static __device__ constexpr float Wc[22] = {
    5.143166e-04f, 1.477931e-03f, 3.800325e-03f, 8.744478e-03f,
    1.800486e-02f, 3.317359e-02f, 5.469392e-02f, 8.069228e-02f,
    1.065293e-01f, 1.258494e-01f, 1.330392e-01f, 1.258494e-01f,
    1.065293e-01f, 8.069228e-02f, 5.469392e-02f, 3.317359e-02f,
    1.800486e-02f, 8.744478e-03f, 3.800325e-03f, 1.477931e-03f,
    5.143166e-04f, 0.0f };

__device__ float g_vox[GRID_ELEMS];   // scatter target; re-zeroed by convz role
__device__ float g_tmp[GRID_ELEMS];   // convXY output, layout [b][y][z][x]
__device__ unsigned g_ticket;
__device__ unsigned g_scat_done[NB];
__device__ unsigned g_cxy_done[NB];

// ---- packed f32x2 helpers --------------------------------------------------
#define PACK2(d, lo, hi) \
    asm("mov.b64 %0, {%1, %2};" : "=l"(d) : "f"(lo), "f"(hi))
#define UNPACK2(lo, hi, s) \
    asm("mov.b64 {%0, %1}, %2;" : "=f"(lo), "=f"(hi) : "l"(s))
#define FMA2(d, a, b, c) \
    asm("fma.rn.f32x2 %0, %1, %2, %3;" : "=l"(d) : "l"(a), "l"(b), "l"(c))

__device__ __forceinline__ unsigned long long wpair(int r) {
    unsigned long long w;
    float lo = (r <= 20) ? Wc[r] : 0.0f;
    float hi = (r >= 1) ? Wc[r - 1] : 0.0f;
    PACK2(w, lo, hi);
    return w;
}

// Value-stationary 21-tap conv, 16 outputs as 8 packed f32x2 accumulators.
#define CONVP8(LOADEXPR, OUTSTMT)                                        \
    {                                                                    \
        unsigned long long acc[8];                                       \
        _Pragma("unroll") for (int p = 0; p < 8; p++) acc[p] = 0ull;     \
        _Pragma("unroll") for (int m = 0; m < 36; m++) {                 \
            float v = (LOADEXPR);                                        \
            unsigned long long vv; PACK2(vv, v, v);                      \
            _Pragma("unroll") for (int p = 0; p < 8; p++) {              \
                if (m >= 2 * p && m <= 2 * p + 21) {                     \
                    FMA2(acc[p], vv, wpair(m - 2 * p), acc[p]);          \
                }                                                        \
            }                                                            \
        }                                                                \
        float o[16];                                                     \
        _Pragma("unroll") for (int p = 0; p < 8; p++)                    \
            UNPACK2(o[2 * p], o[2 * p + 1], acc[p]);                     \
        _Pragma("unroll") for (int j = 0; j < 16; j++) { OUTSTMT; }      \
    }

// ---------------------------------------------------------------------------
// Ticket ordering: steps s=0..33.  Within step s (in order):
//   scatter segment (256 tickets, batch s)        if s < 32
//   convxy  segment ( 64 tickets, batch s-1)      if 1 <= s <= 32
//   convz   segment ( 64 tickets, batch s-2)      if 2 <= s <= 33
// Consumers additionally gate on completion counters, so ordering is a
// performance hint; correctness comes from the counters.
// ---------------------------------------------------------------------------
__device__ __forceinline__ void decode(unsigned T, int& type, int& b, int& idx) {
    for (int s = 0; s < 34; s++) {
        if (s < 32)            { if (T < 256) { type = 0; b = s;     idx = (int)T; return; } T -= 256; }
        if (s >= 1 && s <= 32) { if (T <  64) { type = 1; b = s - 1; idx = (int)T; return; } T -=  64; }
        if (s >= 2)            { if (T <  64) { type = 2; b = s - 2; idx = (int)T; return; } T -=  64; }
    }
    type = -1;
}

__device__ __forceinline__ void wait_count(unsigned* cnt, unsigned target) {
    if (threadIdx.x == 0) {
        while (atomicAdd(cnt, 0u) < target) { }
    }
    __syncthreads();
    __threadfence();
}

// ---------------------------------------------------------------------------
__device__ __forceinline__ void role_scatter(int ci, const float* __restrict__ pc,
                                             const float* __restrict__ rot,
                                             float* SM) {
    int t = threadIdx.x;
    int b = ci >> 8;
    float* R  = SM;          // 9 floats
    float* sp = SM + 16;     // 768 floats
    if (t < 9) R[t] = rot[b * 9 + t];
    const float* pblk = pc + (size_t)ci * 768;
    sp[t]       = pblk[t];
    sp[t + 256] = pblk[t + 256];
    sp[t + 512] = pblk[t + 512];
    __syncthreads();

    float px = sp[t * 3 + 0];
    float py = sp[t * 3 + 1];
    float pz = sp[t * 3 + 2];

    float tx = fmaf(px, R[0], fmaf(py, R[1], pz * R[2]));
    float ty = fmaf(px, R[3], fmaf(py, R[4], pz * R[5]));
    float tz = fmaf(px, R[6], fmaf(py, R[7], pz * R[8]));

    float gx = (tx + 0.5f) * 63.0f;
    float gy = (ty + 0.5f) * 63.0f;
    float gz = (tz + 0.5f) * 63.0f;
    float fx = floorf(gx), fy = floorf(gy), fz = floorf(gz);
    int ix = (int)fx, iy = (int)fy, iz = (int)fz;
    float ax = gx - fx, ay = gy - fy, az = gz - fz;

    float wx0 = 1.0f - ax, wx1 = ax;
    float wy[2] = {1.0f - ay, ay};
    float wz[2] = {1.0f - az, az};

    float* base = g_vox + (size_t)b * S3;
    bool evenfast = ((ix & 1) == 0) && ((unsigned)ix <= 62u);
#pragma unroll
    for (int c = 0; c < 4; c++) {
        int dy = c & 1, dz = c >> 1;
        int Y = iy + dy, Z = iz + dz;
        if ((unsigned)Y >= S || (unsigned)Z >= S) continue;
        float wr = wy[dy] * wz[dz];
        float* row = base + Z * S2 + Y * S;
        if (evenfast) {
            asm volatile("red.global.add.v2.f32 [%0], {%1,%2};"
                         :: "l"(row + ix), "f"(wr * wx0), "f"(wr * wx1)
                         : "memory");
        } else {
            if ((unsigned)ix < S)       atomicAdd(row + ix,     wr * wx0);
            if ((unsigned)(ix + 1) < S) atomicAdd(row + ix + 1, wr * wx1);
        }
    }
    __threadfence();             // make this thread's reds globally visible
    __syncthreads();
    if (t == 0) atomicAdd(&g_scat_done[b], 1u);
}

// ---------------------------------------------------------------------------
__device__ __forceinline__ void role_convxy(int b, int z, float* SM) {
    int bz = b * S + z;
    const float* src = g_vox + (size_t)bz * S2;
    float* dstb = g_tmp + (size_t)b * S3 + z * S;      // + y*S2 + x
    float* A = SM;               // [y][x+10], stride 85 (5440 floats)
    float* B = SM + 5440;        // [y+10][x], stride 65 (5460 floats)
    int t = threadIdx.x;

    for (int i = t; i < S * 85; i += 256) A[i] = 0.0f;
    for (int i = t; i < 10 * 65; i += 256) { B[i] = 0.0f; B[74 * 65 + i] = 0.0f; }
    __syncthreads();
    for (int i = t; i < S2; i += 256) {
        int y = i >> 6, x = i & 63;
        float v = __ldcg(src + i);                     // L2-direct
        A[y * 85 + x + 10] = fminf(fmaxf(v, 0.0f), 1.0f);
    }
    __syncthreads();

    {   // conv X
        int y  = t & 63;
        int x0 = (t >> 6) * 16;
        const float* row = A + y * 85 + x0;
        float* brow = B + (y + 10) * 65 + x0;
        CONVP8(row[m], brow[j] = o[j]);
    }
    __syncthreads();

    {   // conv Y -> transposed store
        int x  = t & 63;
        int y0 = (t >> 6) * 16;
        const float* col = B + y0 * 65 + x;
        float* d = dstb + (size_t)y0 * S2 + x;
        CONVP8(col[m * 65], d[(size_t)j * S2] = o[j]);
    }
    __threadfence();
    __syncthreads();
    if (t == 0) atomicAdd(&g_cxy_done[b], 1u);
}

// ---------------------------------------------------------------------------
__device__ __forceinline__ void role_convz(int b, int y,
                                           const float* __restrict__ scale,
                                           float* __restrict__ out, float* SM) {
    int by = b * S + y;
    const float* src = g_tmp + (size_t)by * S2;        // [z][x] contiguous
    float* Bz   = SM;            // [z+10][x], stride 65 (5460 floats)
    float* part = SM + 5460;     // 4 x 64
    int t = threadIdx.x;

    for (int i = t; i < 10 * 65; i += 256) { Bz[i] = 0.0f; Bz[74 * 65 + i] = 0.0f; }
    for (int i = t; i < S2; i += 256) {
        int z = i >> 6, x = i & 63;
        Bz[(z + 10) * 65 + x] = __ldcg(src + i);
    }
    {   // re-zero this batch's 16KB g_vox chunk for the next replay
        float4* vz = reinterpret_cast<float4*>(g_vox + (size_t)by * S2);
#pragma unroll
        for (int i = 0; i < 4; i++)
            vz[t + 256 * i] = make_float4(0.f, 0.f, 0.f, 0.f);
    }
    __syncthreads();

    float sc = scale[b];
    int x  = t & 63;
    int z0 = (t >> 6) * 16;
    const float* col = Bz + z0 * 65 + x;

    float T = 1.0f;
    CONVP8(col[m * 65],
           { float a = fminf(fmaxf(o[j] * sc, 0.0f), 1.0f); T *= (1.0f - a); });

    part[(t >> 6) * S + x] = T;
    __syncthreads();
    if (t < 64) {
        float Tt = part[x] * part[S + x] * part[2 * S + x] * part[3 * S + x];
        out[(size_t)b * S2 + (63 - y) * S + x] = 1.0f - Tt;
    }
}

// ---------------------------------------------------------------------------
__global__ void k_reset() {
    int t = threadIdx.x;
    if (t == 0) g_ticket = 0;
    if (t < NB) { g_scat_done[t] = 0; g_cxy_done[t] = 0; }
}

__global__ void __launch_bounds__(256) k_mega(const float* __restrict__ pc,
                                              const float* __restrict__ rot,
                                              const float* __restrict__ scale,
                                              float* __restrict__ out) {
    __shared__ float SM[10912];      // union: convxy(10900) / convz(5716) / scatter(784)
    __shared__ unsigned sT;

    while (true) {
        __syncthreads();             // protect SM + sT reuse across tickets
        if (threadIdx.x == 0) sT = atomicAdd(&g_ticket, 1u);
        __syncthreads();
        unsigned T = sT;
        if (T >= N_TICKETS) return;

        int type, b, idx;
        decode(T, type, b, idx);
        if (type == 0) {
            role_scatter(b * 256 + idx, pc, rot, SM);
        } else if (type == 1) {
            wait_count(&g_scat_done[b], 256u);
            role_convxy(b, idx, SM);
        } else {
            wait_count(&g_cxy_done[b], 64u);
            role_convz(b, idx, scale, out, SM);
        }
    }
}

// ---------------------------------------------------------------------------
extern "C" void kernel_launch(void* const* d_in, const int* in_sizes, int n_in,
                              void* d_out, int out_size) {
    const float* pc    = (const float*)d_in[0];
    const float* rot   = (const float*)d_in[1];
    const float* scale = (const float*)d_in[2];
    float* out = (float*)d_out;

    k_reset<<<1, 32>>>();
    k_mega<<<WORKERS, 256>>>(pc, rot, scale, out);
}

// round 17
// speedup vs baseline: 2.1240x; 2.1240x over previous
#include <cuda_runtime.h>

#define NB 32
#define S 64
#define S2 (S*S)
#define S3 (S*S*S)
#define NPTS 65536
#define GRID_ELEMS (NB*S3)

// 21-tap Gaussian, sigma=3, normalized (double-precision derived), + zero pad
static __device__ constexpr float Wc[22] = {
    5.143166e-04f, 1.477931e-03f, 3.800325e-03f, 8.744478e-03f,
    1.800486e-02f, 3.317359e-02f, 5.469392e-02f, 8.069228e-02f,
    1.065293e-01f, 1.258494e-01f, 1.330392e-01f, 1.258494e-01f,
    1.065293e-01f, 8.069228e-02f, 5.469392e-02f, 3.317359e-02f,
    1.800486e-02f, 8.744478e-03f, 3.800325e-03f, 1.477931e-03f,
    5.143166e-04f, 0.0f };

__device__ float g_vox[GRID_ELEMS];   // f32 scatter target; re-zeroed by k_convz
__device__ float g_tmp[GRID_ELEMS];   // convXY output, layout [b][y][z][x]

// ---- packed f32x2 helpers (sm_103a FFMA2 path; PTX-only) -------------------
#define PACK2(d, lo, hi) \
    asm("mov.b64 %0, {%1, %2};" : "=l"(d) : "f"(lo), "f"(hi))
#define UNPACK2(lo, hi, s) \
    asm("mov.b64 {%0, %1}, %2;" : "=f"(lo), "=f"(hi) : "l"(s))
#define FMA2(d, a, b, c) \
    asm("fma.rn.f32x2 %0, %1, %2, %3;" : "=l"(d) : "l"(a), "l"(b), "l"(c))

// Hoist the 22 unique weight pairs (lo -> output 2p: W[r]; hi -> 2p+1: W[r-1])
// into registers ONCE per kernel. R10 rebuilt these per use (~3 instr x 176),
// which cancelled the FMA2 instruction savings.
#define MAKE_WPAIRS(wp)                                                  \
    _Pragma("unroll") for (int r = 0; r < 22; r++) {                     \
        float lo = (r <= 20) ? Wc[r] : 0.0f;                             \
        float hi = (r >= 1) ? Wc[r - 1] : 0.0f;                          \
        PACK2(wp[r], lo, hi);                                            \
    }

// Value-stationary 21-tap conv, 16 outputs as 8 packed f32x2 accumulators,
// weight pairs pre-hoisted in wp[22]. FMA order identical to R10's CONVP8.
#define CONVP8H(wp, LOADEXPR, OUTSTMT)                                   \
    {                                                                    \
        unsigned long long acc[8];                                       \
        _Pragma("unroll") for (int p = 0; p < 8; p++) acc[p] = 0ull;     \
        _Pragma("unroll") for (int m = 0; m < 36; m++) {                 \
            float v = (LOADEXPR);                                        \
            unsigned long long vv; PACK2(vv, v, v);                      \
            _Pragma("unroll") for (int p = 0; p < 8; p++) {              \
                if (m >= 2 * p && m <= 2 * p + 21) {                     \
                    FMA2(acc[p], vv, wp[m - 2 * p], acc[p]);             \
                }                                                        \
            }                                                            \
        }                                                                \
        float o[16];                                                     \
        _Pragma("unroll") for (int p = 0; p < 8; p++)                    \
            UNPACK2(o[2 * p], o[2 * p + 1], acc[p]);                     \
        _Pragma("unroll") for (int j = 0; j < 16; j++) { OUTSTMT; }      \
    }

// ---------------------------------------------------------------------------
// Rotate points + trilinear scatter (champion form: one 256-point chunk per
// block, red.v2.f32 fast path). LTS-lane-floor bound, ~50us.
// ---------------------------------------------------------------------------
__global__ void k_scatter(const float* __restrict__ pc,
                          const float* __restrict__ rot) {
    int t = threadIdx.x;
    int b = blockIdx.x >> 8;                     // 256 blocks per batch
    __shared__ float R[9];
    __shared__ float sp[768];                    // 256 points * 3
    if (t < 9) R[t] = rot[b * 9 + t];
    const float* pblk = pc + (size_t)blockIdx.x * 768;
    sp[t]       = pblk[t];
    sp[t + 256] = pblk[t + 256];
    sp[t + 512] = pblk[t + 512];
    __syncthreads();

    float px = sp[t * 3 + 0];
    float py = sp[t * 3 + 1];
    float pz = sp[t * 3 + 2];

    float tx = fmaf(px, R[0], fmaf(py, R[1], pz * R[2]));
    float ty = fmaf(px, R[3], fmaf(py, R[4], pz * R[5]));
    float tz = fmaf(px, R[6], fmaf(py, R[7], pz * R[8]));

    float gx = (tx + 0.5f) * 63.0f;
    float gy = (ty + 0.5f) * 63.0f;
    float gz = (tz + 0.5f) * 63.0f;
    float fx = floorf(gx), fy = floorf(gy), fz = floorf(gz);
    int ix = (int)fx, iy = (int)fy, iz = (int)fz;
    float ax = gx - fx, ay = gy - fy, az = gz - fz;

    float wx0 = 1.0f - ax, wx1 = ax;
    float wy[2] = {1.0f - ay, ay};
    float wz[2] = {1.0f - az, az};

    float* base = g_vox + (size_t)b * S3;
    bool evenfast = ((ix & 1) == 0) && ((unsigned)ix <= 62u);
#pragma unroll
    for (int c = 0; c < 4; c++) {
        int dy = c & 1, dz = c >> 1;
        int Y = iy + dy, Z = iz + dz;
        if ((unsigned)Y >= S || (unsigned)Z >= S) continue;
        float wr = wy[dy] * wz[dz];
        float* row = base + Z * S2 + Y * S;
        if (evenfast) {
            asm volatile("red.global.add.v2.f32 [%0], {%1,%2};"
                         :: "l"(row + ix), "f"(wr * wx0), "f"(wr * wx1)
                         : "memory");
        } else {
            if ((unsigned)ix < S)       atomicAdd(row + ix,     wr * wx0);
            if ((unsigned)(ix + 1) < S) atomicAdd(row + ix + 1, wr * wx1);
        }
    }
}

// ---------------------------------------------------------------------------
// Fused conv along X then Y (clip raw voxels on load). One block per (b,z).
// Output layout transposed: g_tmp[b][y][z][x] so convz reads contiguously.
// Only A's pad columns are zeroed (interior fully overwritten by the fill).
// ---------------------------------------------------------------------------
__global__ void __launch_bounds__(256) k_convxy() {
    int bz = blockIdx.x;
    int b = bz >> 6, z = bz & 63;
    const float* src = g_vox + (size_t)bz * S2;
    float* dstb = g_tmp + (size_t)b * S3 + z * S;      // + y*S2 + x
    __shared__ float A[S * 85];      // [y][x+10], x pads zeroed
    __shared__ float B[84 * 65];     // [y+10][x], y pads zeroed
    int t = threadIdx.x;

    unsigned long long wp[22];
    MAKE_WPAIRS(wp);

    // zero A pad cols (0..9, 74..83; col 84 never read) and B pad rows
    for (int i = t; i < 64 * 20; i += 256) {
        int row = i / 20, c = i % 20;
        int col = (c < 10) ? c : (64 + c);
        A[row * 85 + col] = 0.0f;
    }
    for (int i = t; i < 10 * 65; i += 256) { B[i] = 0.0f; B[74 * 65 + i] = 0.0f; }
    __syncthreads();
    for (int i = t; i < S2; i += 256) {
        int y = i >> 6, x = i & 63;
        float v = src[i];
        A[y * 85 + x + 10] = fminf(fmaxf(v, 0.0f), 1.0f);
    }
    __syncthreads();

    {   // conv X: warp = 32 consecutive y (stride 85 -> conflict-free)
        int y  = t & 63;
        int x0 = (t >> 6) * 16;
        const float* row = A + y * 85 + x0;
        float* brow = B + (y + 10) * 65 + x0;
        CONVP8H(wp, row[m], brow[j] = o[j]);
    }
    __syncthreads();

    {   // conv Y: warp = 32 consecutive x (stride 1 -> conflict-free)
        int x  = t & 63;
        int y0 = (t >> 6) * 16;
        const float* col = B + y0 * 65 + x;
        float* d = dstb + (size_t)y0 * S2 + x;          // [b][y][z][x]
        CONVP8H(wp, col[m * 65], d[(size_t)j * S2] = o[j]);
    }
}

// ---------------------------------------------------------------------------
// Conv along Z + scale + clip + DRC product + flip. One block per (b,y).
// Reads g_tmp[b][y][:][:] contiguously (16KB). Re-zeroes its g_vox chunk.
// ---------------------------------------------------------------------------
__global__ void __launch_bounds__(256) k_convz(const float* __restrict__ scale,
                                               float* __restrict__ out) {
    int by = blockIdx.x;
    int b = by >> 6, y = by & 63;
    const float* src = g_tmp + (size_t)by * S2;     // [z][x] contiguous
    __shared__ float Bz[84 * 65];    // [z+10][x]
    __shared__ float part[4][S];
    int t = threadIdx.x;

    unsigned long long wp[22];
    MAKE_WPAIRS(wp);

    for (int i = t; i < 10 * 65; i += 256) { Bz[i] = 0.0f; Bz[74 * 65 + i] = 0.0f; }
    for (int i = t; i < S2; i += 256) {
        int z = i >> 6, x = i & 63;
        Bz[(z + 10) * 65 + x] = src[i];
    }
    {   // re-zero this block's chunk of the voxel grid for next replay
        float4* vz = reinterpret_cast<float4*>(g_vox + (size_t)by * S2);
#pragma unroll
        for (int i = 0; i < 4; i++)
            vz[t + 256 * i] = make_float4(0.f, 0.f, 0.f, 0.f);
    }
    __syncthreads();

    float sc = scale[b];
    int x  = t & 63;
    int z0 = (t >> 6) * 16;
    const float* col = Bz + z0 * 65 + x;

    float T = 1.0f;
    CONVP8H(wp, col[m * 65],
            { float a = fminf(fmaxf(o[j] * sc, 0.0f), 1.0f); T *= (1.0f - a); });

    part[t >> 6][x] = T;
    __syncthreads();
    if (t < 64) {
        float Tt = part[0][x] * part[1][x] * part[2][x] * part[3][x];
        out[(size_t)b * S2 + (63 - y) * S + x] = 1.0f - Tt;
    }
}

// ---------------------------------------------------------------------------
extern "C" void kernel_launch(void* const* d_in, const int* in_sizes, int n_in,
                              void* d_out, int out_size) {
    const float* pc    = (const float*)d_in[0];
    const float* rot   = (const float*)d_in[1];
    const float* scale = (const float*)d_in[2];
    float* out = (float*)d_out;

    k_scatter<<<NB * NPTS / 256, 256>>>(pc, rot);
    k_convxy<<<NB * S, 256>>>();
    k_convz<<<NB * S, 256>>>(scale, out);
}